// round 14
// baseline (speedup 1.0000x reference)
#include <cuda_runtime.h>
#include <cstddef>
#include <cstdint>

#define BB 8
#define TE 2048
#define TD 256
#define HH 128

#define TT 64     // t-tile in score kernel
#define TJ 8      // j-tile in score kernel (one warp per j)

#define JT 16     // j-tile in fused softmax+context kernel
#define TC 64     // t-chunk in context kernel

typedef unsigned long long ull;

// Scratch (allocation-free per harness rules)
__device__ unsigned short g_WencH[BB * TE * HH];  // f16 tiled [b][t/64][k][t%64]
__device__ unsigned g_UdecH[BB * TD * HH];        // dup half2(u,u) [b][j][k]

__device__ __forceinline__ void fma2(ull& acc, ull a, ull b) {
    asm("fma.rn.f32x2 %0, %1, %2, %0;" : "+l"(acc) : "l"(a), "l"(b));
}
__device__ __forceinline__ ull pack2(float lo, float hi) {
    ull r; asm("mov.b64 %0, {%1, %2};" : "=l"(r) : "f"(lo), "f"(hi)); return r;
}
__device__ __forceinline__ void unpack2(ull v, float& lo, float& hi) {
    asm("mov.b64 {%0, %1}, %2;" : "=f"(lo), "=f"(hi) : "l"(v));
}

// ---------------------------------------------------------------------------
// K0 (fused): both projections in one launch, 32 rows per block. (R10 exact)
// ---------------------------------------------------------------------------
__global__ void proj_kernel(const float* __restrict__ enc,
                            const float* __restrict__ dec,
                            const float* __restrict__ Wa,
                            const float* __restrict__ Ua) {
    __shared__ float Ws[64 * HH];    // 32 KB
    __shared__ float ins[32 * HH];   // 16 KB

    int tid = threadIdx.x;                  // 256 threads
    int which = (blockIdx.x >= BB * TE / 32) ? 1 : 0;
    int blk   = which ? (blockIdx.x - BB * TE / 32) : blockIdx.x;
    const float* in = which ? dec : enc;
    const float* Wm = which ? Ua : Wa;
    int row0 = blk * 32;

    const float4* in4 = (const float4*)(in + (size_t)row0 * HH);
    float4* ins4 = (float4*)ins;
#pragma unroll
    for (int i = 0; i < 4; i++) ins4[tid + i * 256] = in4[tid + i * 256];

    int k2 = tid & 63;    // k = {2k2, 2k2+1}
    int g  = tid >> 6;    // rows g*8 .. g*8+7

    ull acc[8];
#pragma unroll
    for (int r = 0; r < 8; r++) acc[r] = 0ull;

    for (int hc = 0; hc < HH; hc += 64) {
        __syncthreads();
        const float4* W4 = (const float4*)(Wm + hc * HH);
        float4* Ws4 = (float4*)Ws;
#pragma unroll
        for (int i = 0; i < 8; i++) Ws4[tid + i * 256] = W4[tid + i * 256];
        __syncthreads();

#pragma unroll 1
        for (int h4 = 0; h4 < 64; h4 += 4) {
            float4 iv[8];
#pragma unroll
            for (int r = 0; r < 8; r++)
                iv[r] = *(const float4*)&ins[(g * 8 + r) * HH + hc + h4];
#pragma unroll
            for (int dh = 0; dh < 4; dh++) {
                ull wv2 = *(const ull*)&Ws[(h4 + dh) * HH + 2 * k2];  // LDS.64
#pragma unroll
                for (int r = 0; r < 8; r++) {
                    float ev = (&iv[r].x)[dh];
                    fma2(acc[r], wv2, pack2(ev, ev));
                }
            }
        }
    }

    float ax[8], ay[8];
#pragma unroll
    for (int r = 0; r < 8; r++) unpack2(acc[r], ax[r], ay[r]);

    int r0 = row0 + g * 8;
    if (which == 0) {
        int b   = r0 / TE;
        int t   = r0 % TE;
        int tb  = t / 64;
        int tl0 = t % 64;    // multiple of 8
        unsigned ex[4], ey[4];
#pragma unroll
        for (int m = 0; m < 4; m++) {
            asm("cvt.rn.f16x2.f32 %0, %1, %2;"
                : "=r"(ex[m]) : "f"(ax[2 * m + 1]), "f"(ax[2 * m]));
            asm("cvt.rn.f16x2.f32 %0, %1, %2;"
                : "=r"(ey[m]) : "f"(ay[2 * m + 1]), "f"(ay[2 * m]));
        }
        size_t base = (size_t)(b * (TE / 64) + tb) * HH * 64;
        *(uint4*)(g_WencH + base + (size_t)(2 * k2 + 0) * 64 + tl0) =
            make_uint4(ex[0], ex[1], ex[2], ex[3]);
        *(uint4*)(g_WencH + base + (size_t)(2 * k2 + 1) * 64 + tl0) =
            make_uint4(ey[0], ey[1], ey[2], ey[3]);
    } else {
#pragma unroll
        for (int r = 0; r < 8; r++) {
            unsigned d0, d1;
            asm("cvt.rn.f16x2.f32 %0, %1, %1;" : "=r"(d0) : "f"(ax[r]));  // (u,u)
            asm("cvt.rn.f16x2.f32 %0, %1, %1;" : "=r"(d1) : "f"(ay[r]));
            *(uint2*)(g_UdecH + (size_t)(r0 + r) * HH + 2 * k2) = make_uint2(d0, d1);
        }
    }
}

// ---------------------------------------------------------------------------
// K1: raw scores s[b,j,t] = sum_k V[k]*tanh(Wenc[b,t,k]+Udec[b,j,k])
// Pure MUFU mainloop (R10 exact — fastest measured). Raw scores to e_out.
// ---------------------------------------------------------------------------
__global__ void score_kernel(const float* __restrict__ Va,
                             float* __restrict__ e_out) {
    __shared__ __align__(16) unsigned short Weh[TT * HH];  // 16 KB
    __shared__ __align__(16) unsigned Udh[TJ * HH];        // 4 KB
    __shared__ __align__(16) float2 Vs2[HH];               // 1 KB

    int tid = threadIdx.x;            // 256
    int b  = blockIdx.z;
    int jb = blockIdx.y;
    int tb = blockIdx.x;

    {
        const uint4* src = (const uint4*)(g_WencH +
            (size_t)(b * (TE / 64) + tb) * (HH * 64));
        uint4* dst = (uint4*)Weh;
#pragma unroll
        for (int i = 0; i < 4; i++) dst[tid + i * 256] = src[tid + i * 256];
    }
    {
        const uint4* us = (const uint4*)(g_UdecH + ((size_t)b * TD + jb * TJ) * HH);
        ((uint4*)Udh)[tid] = us[tid];
    }
    if (tid < HH) { float v = Va[tid]; Vs2[tid] = make_float2(v, v); }
    __syncthreads();

    int w = tid >> 5;      // local j
    int lane = tid & 31;

    const unsigned* Wp = (const unsigned*)Weh + lane;   // + k*32 per k
    const unsigned* Up = Udh + w * HH;

    ull acc01 = 0ull;   // packed f32x2 (even-t, odd-t)

#pragma unroll 4
    for (int k = 0; k < HH; k++) {
        unsigned wx = Wp[k * 32];      // (t=2l, t=2l+1) halves
        unsigned ux = Up[k];           // (u, u)
        unsigned x2;
        asm("add.rn.f16x2 %0, %1, %2;" : "=r"(x2) : "r"(wx), "r"(ux));
        asm("tanh.approx.f16x2 %0, %0;" : "+r"(x2));
        float flo, fhi;
        asm("{ .reg .b16 lo, hi;\n\t"
            "  mov.b32 {lo, hi}, %2;\n\t"
            "  cvt.f32.f16 %0, lo;\n\t"
            "  cvt.f32.f16 %1, hi; }"
            : "=f"(flo), "=f"(fhi) : "r"(x2));
        fma2(acc01, pack2(flo, fhi), *(const ull*)&Vs2[k]);
    }

    float ae, ao;
    unpack2(acc01, ae, ao);

    int j = jb * TJ + w;
    size_t base = ((size_t)b * TD + j) * TE + tb * TT;
    *(float2*)(e_out + base + 2 * lane) = make_float2(ae, ao);
}

// ---------------------------------------------------------------------------
// K2 (fused softmax + context), JT=16, direct-LDG enc (no enc staging):
// Pass 1: per-row max + exp-sum over raw scores (L2-hot) — R10 exact.
// Pass 2: stage ONLY the e tile (normalize + write back); enc rows are read
// straight from gmem in the mainloop (4 jg-warps share addresses -> L1 hits;
// L2 traffic unchanged; removes 8 LDG + 8 STS + 32 LDS per thread per chunk
// and shrinks the per-chunk sync critical path to the tiny es stage).
// ---------------------------------------------------------------------------
__global__ void context_kernel(const float* __restrict__ enc,
                               float* __restrict__ e,
                               float* __restrict__ c) {
    __shared__ float es[JT * TC];       // 4 KB
    __shared__ float red[4 * 32 * 16];  // 8 KB (t-split reduction)
    __shared__ float sm_m[JT], sm_inv[JT];

    int tid = threadIdx.x;            // 256
    int bj = blockIdx.x;              // 0..127
    int b  = bj >> 4;                 // TD/JT = 16
    int jb = bj & 15;

    int wid  = tid >> 5;
    int lane = tid & 31;

    // ---- pass 1: softmax stats, warp wid -> rows {2wid, 2wid+1} ----
#pragma unroll
    for (int rr = 0; rr < 2; rr++) {
        int row = wid * 2 + rr;
        const float4* p4 = (const float4*)(e + ((size_t)(b * TD + jb * JT + row)) * TE);
        float m = -1e30f;
#pragma unroll
        for (int i = 0; i < 16; i++) {
            float4 v = p4[lane + i * 32];
            m = fmaxf(m, fmaxf(fmaxf(v.x, v.y), fmaxf(v.z, v.w)));
        }
#pragma unroll
        for (int o = 16; o; o >>= 1) m = fmaxf(m, __shfl_xor_sync(0xffffffffu, m, o));
        float s = 0.0f;
#pragma unroll
        for (int i = 0; i < 16; i++) {
            float4 v = p4[lane + i * 32];
            s += __expf(v.x - m) + __expf(v.y - m) + __expf(v.z - m) + __expf(v.w - m);
        }
#pragma unroll
        for (int o = 16; o; o >>= 1) s += __shfl_xor_sync(0xffffffffu, s, o);
        if (lane == 0) { sm_m[row] = m; sm_inv[row] = __fdividef(1.0f, s); }
    }
    __syncthreads();

    int ts = wid >> 2;                // 0..1 t-half
    int jg = wid & 3;                 // 0..3 (4 j each)

    ull acc[4][2];
#pragma unroll
    for (int j = 0; j < 4; j++) { acc[j][0] = 0ull; acc[j][1] = 0ull; }

    for (int tc = 0; tc < TE; tc += TC) {
        __syncthreads();
        {   // stage + normalize + write back e tile (16 rows x 16 float4)
            int jj = tid >> 4, c4 = tid & 15;
            float* gp = e + ((size_t)(b * TD + jb * JT + jj)) * TE + tc;
            float4 x = ((const float4*)gp)[c4];
            float mm = sm_m[jj], iv = sm_inv[jj];
            x.x = __expf(x.x - mm) * iv;
            x.y = __expf(x.y - mm) * iv;
            x.z = __expf(x.z - mm) * iv;
            x.w = __expf(x.w - mm) * iv;
            ((float4*)es)[tid] = x;
            ((float4*)gp)[c4]  = x;
        }
        __syncthreads();

        const float4* es4 = (const float4*)es;
        const float* encb = enc + ((size_t)b * TE + tc) * HH + 4 * lane;
#pragma unroll 2
        for (int t0 = ts * 32; t0 < ts * 32 + 32; t0 += 4) {
            float4 ev0 = es4[(jg * 4 + 0) * 16 + (t0 >> 2)];
            float4 ev1 = es4[(jg * 4 + 1) * 16 + (t0 >> 2)];
            float4 ev2 = es4[(jg * 4 + 2) * 16 + (t0 >> 2)];
            float4 ev3 = es4[(jg * 4 + 3) * 16 + (t0 >> 2)];
#pragma unroll
            for (int dt = 0; dt < 4; dt++) {
                float4 en = *(const float4*)(encb + (size_t)(t0 + dt) * HH);
                ull en01 = pack2(en.x, en.y);
                ull en23 = pack2(en.z, en.w);
                float e0 = (&ev0.x)[dt], e1 = (&ev1.x)[dt];
                float e2 = (&ev2.x)[dt], e3 = (&ev3.x)[dt];
                ull ee;
                ee = pack2(e0, e0); fma2(acc[0][0], en01, ee); fma2(acc[0][1], en23, ee);
                ee = pack2(e1, e1); fma2(acc[1][0], en01, ee); fma2(acc[1][1], en23, ee);
                ee = pack2(e2, e2); fma2(acc[2][0], en01, ee); fma2(acc[2][1], en23, ee);
                ee = pack2(e3, e3); fma2(acc[3][0], en01, ee); fma2(acc[3][1], en23, ee);
            }
        }
    }

    // 2-way t-split reduction via smem (16 floats per (jg,lane))
    __syncthreads();
    if (ts == 1) {
        float* dst = red + (size_t)(jg * 32 + lane) * 16;
#pragma unroll
        for (int j = 0; j < 4; j++) {
            unpack2(acc[j][0], dst[j * 4 + 0], dst[j * 4 + 1]);
            unpack2(acc[j][1], dst[j * 4 + 2], dst[j * 4 + 3]);
        }
    }
    __syncthreads();
    if (ts == 0) {
        const float* src = red + (size_t)(jg * 32 + lane) * 16;
        int jbase = b * TD + jb * JT + jg * 4;
#pragma unroll
        for (int j = 0; j < 4; j++) {
            float x0, x1, x2, x3;
            unpack2(acc[j][0], x0, x1);
            unpack2(acc[j][1], x2, x3);
            float4 r = make_float4(x0 + src[j * 4 + 0], x1 + src[j * 4 + 1],
                                   x2 + src[j * 4 + 2], x3 + src[j * 4 + 3]);
            *(float4*)(c + (size_t)(jbase + j) * HH + 4 * lane) = r;
        }
    }
}

// ---------------------------------------------------------------------------
// Launch: c_outputs [B,TD,H] then e_outputs [B,TD,TE], flattened in order.
// ---------------------------------------------------------------------------
extern "C" void kernel_launch(void* const* d_in, const int* in_sizes, int n_in,
                              void* d_out, int out_size) {
    const float* enc = (const float*)d_in[0];   // [B,TE,H]
    const float* dec = (const float*)d_in[1];   // [B,TD,D]
    const float* Wa  = (const float*)d_in[2];   // [H,H]
    const float* Ua  = (const float*)d_in[3];   // [D,H]
    const float* Va  = (const float*)d_in[4];   // [H,1]

    float* out   = (float*)d_out;
    float* c_out = out;                          // B*TD*H
    float* e_out = out + (size_t)BB * TD * HH;   // B*TD*TE

    proj_kernel<<<BB * TE / 32 + BB * TD / 32, 256>>>(enc, dec, Wa, Ua);
    score_kernel<<<dim3(TE / TT, TD / TJ, BB), 256>>>(Va, e_out);
    context_kernel<<<BB * TD / JT, 256>>>(enc, e_out, c_out);
}

// round 15
// speedup vs baseline: 1.1977x; 1.1977x over previous
#include <cuda_runtime.h>
#include <cstddef>
#include <cstdint>

#define BB 8
#define TE 2048
#define TD 256
#define HH 128

#define TT 64     // t-tile in score kernel
#define TJ 8      // j-tile in score kernel (one warp per j)

#define JT 16     // j-tile in fused softmax+context kernel
#define TC 64     // t-chunk in context kernel

typedef unsigned long long ull;

// Scratch (allocation-free per harness rules)
__device__ unsigned short g_WencH[BB * TE * HH];  // f16 tiled [b][t/64][k][t%64]
__device__ unsigned g_UdecH[BB * TD * HH];        // dup half2(u,u) [b][j][k]

__device__ __forceinline__ void fma2(ull& acc, ull a, ull b) {
    asm("fma.rn.f32x2 %0, %1, %2, %0;" : "+l"(acc) : "l"(a), "l"(b));
}
__device__ __forceinline__ ull pack2(float lo, float hi) {
    ull r; asm("mov.b64 %0, {%1, %2};" : "=l"(r) : "f"(lo), "f"(hi)); return r;
}
__device__ __forceinline__ void unpack2(ull v, float& lo, float& hi) {
    asm("mov.b64 {%0, %1}, %2;" : "=f"(lo), "=f"(hi) : "l"(v));
}

// ---------------------------------------------------------------------------
// K0 (fused): both projections in one launch, 32 rows per block.
// __launch_bounds__(256, 4): cap regs at 64 so 4 blocks fit per SM
// (R10 measured 66 regs -> 3 blocks, occ 31%, issue 42% = latency-bound).
// ---------------------------------------------------------------------------
__global__ void __launch_bounds__(256, 4)
proj_kernel(const float* __restrict__ enc,
            const float* __restrict__ dec,
            const float* __restrict__ Wa,
            const float* __restrict__ Ua) {
    __shared__ float Ws[64 * HH];    // 32 KB
    __shared__ float ins[32 * HH];   // 16 KB

    int tid = threadIdx.x;                  // 256 threads
    int which = (blockIdx.x >= BB * TE / 32) ? 1 : 0;
    int blk   = which ? (blockIdx.x - BB * TE / 32) : blockIdx.x;
    const float* in = which ? dec : enc;
    const float* Wm = which ? Ua : Wa;
    int row0 = blk * 32;

    const float4* in4 = (const float4*)(in + (size_t)row0 * HH);
    float4* ins4 = (float4*)ins;
#pragma unroll
    for (int i = 0; i < 4; i++) ins4[tid + i * 256] = in4[tid + i * 256];

    int k2 = tid & 63;    // k = {2k2, 2k2+1}
    int g  = tid >> 6;    // rows g*8 .. g*8+7

    ull acc[8];
#pragma unroll
    for (int r = 0; r < 8; r++) acc[r] = 0ull;

    for (int hc = 0; hc < HH; hc += 64) {
        __syncthreads();
        const float4* W4 = (const float4*)(Wm + hc * HH);
        float4* Ws4 = (float4*)Ws;
#pragma unroll
        for (int i = 0; i < 8; i++) Ws4[tid + i * 256] = W4[tid + i * 256];
        __syncthreads();

#pragma unroll 1
        for (int h4 = 0; h4 < 64; h4 += 4) {
            float4 iv[8];
#pragma unroll
            for (int r = 0; r < 8; r++)
                iv[r] = *(const float4*)&ins[(g * 8 + r) * HH + hc + h4];
#pragma unroll
            for (int dh = 0; dh < 4; dh++) {
                ull wv2 = *(const ull*)&Ws[(h4 + dh) * HH + 2 * k2];  // LDS.64
#pragma unroll
                for (int r = 0; r < 8; r++) {
                    float ev = (&iv[r].x)[dh];
                    fma2(acc[r], wv2, pack2(ev, ev));
                }
            }
        }
    }

    float ax[8], ay[8];
#pragma unroll
    for (int r = 0; r < 8; r++) unpack2(acc[r], ax[r], ay[r]);

    int r0 = row0 + g * 8;
    if (which == 0) {
        int b   = r0 / TE;
        int t   = r0 % TE;
        int tb  = t / 64;
        int tl0 = t % 64;    // multiple of 8
        unsigned ex[4], ey[4];
#pragma unroll
        for (int m = 0; m < 4; m++) {
            asm("cvt.rn.f16x2.f32 %0, %1, %2;"
                : "=r"(ex[m]) : "f"(ax[2 * m + 1]), "f"(ax[2 * m]));
            asm("cvt.rn.f16x2.f32 %0, %1, %2;"
                : "=r"(ey[m]) : "f"(ay[2 * m + 1]), "f"(ay[2 * m]));
        }
        size_t base = (size_t)(b * (TE / 64) + tb) * HH * 64;
        *(uint4*)(g_WencH + base + (size_t)(2 * k2 + 0) * 64 + tl0) =
            make_uint4(ex[0], ex[1], ex[2], ex[3]);
        *(uint4*)(g_WencH + base + (size_t)(2 * k2 + 1) * 64 + tl0) =
            make_uint4(ey[0], ey[1], ey[2], ey[3]);
    } else {
#pragma unroll
        for (int r = 0; r < 8; r++) {
            unsigned d0, d1;
            asm("cvt.rn.f16x2.f32 %0, %1, %1;" : "=r"(d0) : "f"(ax[r]));  // (u,u)
            asm("cvt.rn.f16x2.f32 %0, %1, %1;" : "=r"(d1) : "f"(ay[r]));
            *(uint2*)(g_UdecH + (size_t)(r0 + r) * HH + 2 * k2) = make_uint2(d0, d1);
        }
    }
}

// ---------------------------------------------------------------------------
// K1: raw scores s[b,j,t] = sum_k V[k]*tanh(Wenc[b,t,k]+Udec[b,j,k])
// Pure MUFU mainloop (fastest measured form). Raw scores to e_out.
// ---------------------------------------------------------------------------
__global__ void score_kernel(const float* __restrict__ Va,
                             float* __restrict__ e_out) {
    __shared__ __align__(16) unsigned short Weh[TT * HH];  // 16 KB
    __shared__ __align__(16) unsigned Udh[TJ * HH];        // 4 KB
    __shared__ __align__(16) float2 Vs2[HH];               // 1 KB

    int tid = threadIdx.x;            // 256
    int b  = blockIdx.z;
    int jb = blockIdx.y;
    int tb = blockIdx.x;

    {
        const uint4* src = (const uint4*)(g_WencH +
            (size_t)(b * (TE / 64) + tb) * (HH * 64));
        uint4* dst = (uint4*)Weh;
#pragma unroll
        for (int i = 0; i < 4; i++) dst[tid + i * 256] = src[tid + i * 256];
    }
    {
        const uint4* us = (const uint4*)(g_UdecH + ((size_t)b * TD + jb * TJ) * HH);
        ((uint4*)Udh)[tid] = us[tid];
    }
    if (tid < HH) { float v = Va[tid]; Vs2[tid] = make_float2(v, v); }
    __syncthreads();

    int w = tid >> 5;      // local j
    int lane = tid & 31;

    const unsigned* Wp = (const unsigned*)Weh + lane;   // + k*32 per k
    const unsigned* Up = Udh + w * HH;

    ull acc01 = 0ull;   // packed f32x2 (even-t, odd-t)

#pragma unroll 4
    for (int k = 0; k < HH; k++) {
        unsigned wx = Wp[k * 32];      // (t=2l, t=2l+1) halves
        unsigned ux = Up[k];           // (u, u)
        unsigned x2;
        asm("add.rn.f16x2 %0, %1, %2;" : "=r"(x2) : "r"(wx), "r"(ux));
        asm("tanh.approx.f16x2 %0, %0;" : "+r"(x2));
        float flo, fhi;
        asm("{ .reg .b16 lo, hi;\n\t"
            "  mov.b32 {lo, hi}, %2;\n\t"
            "  cvt.f32.f16 %0, lo;\n\t"
            "  cvt.f32.f16 %1, hi; }"
            : "=f"(flo), "=f"(fhi) : "r"(x2));
        fma2(acc01, pack2(flo, fhi), *(const ull*)&Vs2[k]);
    }

    float ae, ao;
    unpack2(acc01, ae, ao);

    int j = jb * TJ + w;
    size_t base = ((size_t)b * TD + j) * TE + tb * TT;
    *(float2*)(e_out + base + 2 * lane) = make_float2(ae, ao);
}

// ---------------------------------------------------------------------------
// K2 (fused softmax + context), JT=16, smem-staged enc (R10 exact):
// Pass 1: per-row max + exp-sum (8 warps x 2 rows) over raw scores (L2-hot).
// Pass 2: stage enc + e tiles; e normalized on the fly and written back.
// ---------------------------------------------------------------------------
__global__ void context_kernel(const float* __restrict__ enc,
                               float* __restrict__ e,
                               float* __restrict__ c) {
    __shared__ float encs[TC * HH];   // 32 KB (reused for reduction)
    __shared__ float es[JT * TC];     // 4 KB
    __shared__ float sm_m[JT], sm_inv[JT];

    int tid = threadIdx.x;            // 256
    int bj = blockIdx.x;              // 0..127
    int b  = bj >> 4;                 // TD/JT = 16
    int jb = bj & 15;

    int wid  = tid >> 5;
    int lane = tid & 31;

    // ---- pass 1: softmax stats, warp wid -> rows {2wid, 2wid+1} ----
#pragma unroll
    for (int rr = 0; rr < 2; rr++) {
        int row = wid * 2 + rr;
        const float4* p4 = (const float4*)(e + ((size_t)(b * TD + jb * JT + row)) * TE);
        float m = -1e30f;
#pragma unroll
        for (int i = 0; i < 16; i++) {
            float4 v = p4[lane + i * 32];
            m = fmaxf(m, fmaxf(fmaxf(v.x, v.y), fmaxf(v.z, v.w)));
        }
#pragma unroll
        for (int o = 16; o; o >>= 1) m = fmaxf(m, __shfl_xor_sync(0xffffffffu, m, o));
        float s = 0.0f;
#pragma unroll
        for (int i = 0; i < 16; i++) {
            float4 v = p4[lane + i * 32];
            s += __expf(v.x - m) + __expf(v.y - m) + __expf(v.z - m) + __expf(v.w - m);
        }
#pragma unroll
        for (int o = 16; o; o >>= 1) s += __shfl_xor_sync(0xffffffffu, s, o);
        if (lane == 0) { sm_m[row] = m; sm_inv[row] = __fdividef(1.0f, s); }
    }
    __syncthreads();

    int ts = wid >> 2;                // 0..1 t-half
    int jg = wid & 3;                 // 0..3 (4 j each)

    ull acc[4][2];
#pragma unroll
    for (int j = 0; j < 4; j++) { acc[j][0] = 0ull; acc[j][1] = 0ull; }

    for (int tc = 0; tc < TE; tc += TC) {
        __syncthreads();
        {
            const float4* src = (const float4*)(enc + ((size_t)b * TE + tc) * HH);
            float4* d4 = (float4*)encs;
#pragma unroll
            for (int i = 0; i < 8; i++) d4[tid + i * 256] = src[tid + i * 256];
        }
        {   // stage + normalize + write back e tile (16 rows x 16 float4)
            int jj = tid >> 4, c4 = tid & 15;
            float* gp = e + ((size_t)(b * TD + jb * JT + jj)) * TE + tc;
            float4 x = ((const float4*)gp)[c4];
            float mm = sm_m[jj], iv = sm_inv[jj];
            x.x = __expf(x.x - mm) * iv;
            x.y = __expf(x.y - mm) * iv;
            x.z = __expf(x.z - mm) * iv;
            x.w = __expf(x.w - mm) * iv;
            ((float4*)es)[tid] = x;
            ((float4*)gp)[c4]  = x;
        }
        __syncthreads();

        const float4* es4   = (const float4*)es;
        const float4* encs4 = (const float4*)encs;
#pragma unroll 2
        for (int t0 = ts * 32; t0 < ts * 32 + 32; t0 += 4) {
            float4 ev0 = es4[(jg * 4 + 0) * 16 + (t0 >> 2)];
            float4 ev1 = es4[(jg * 4 + 1) * 16 + (t0 >> 2)];
            float4 ev2 = es4[(jg * 4 + 2) * 16 + (t0 >> 2)];
            float4 ev3 = es4[(jg * 4 + 3) * 16 + (t0 >> 2)];
#pragma unroll
            for (int dt = 0; dt < 4; dt++) {
                float4 en = encs4[(t0 + dt) * 32 + lane];
                ull en01 = pack2(en.x, en.y);
                ull en23 = pack2(en.z, en.w);
                float e0 = (&ev0.x)[dt], e1 = (&ev1.x)[dt];
                float e2 = (&ev2.x)[dt], e3 = (&ev3.x)[dt];
                ull ee;
                ee = pack2(e0, e0); fma2(acc[0][0], en01, ee); fma2(acc[0][1], en23, ee);
                ee = pack2(e1, e1); fma2(acc[1][0], en01, ee); fma2(acc[1][1], en23, ee);
                ee = pack2(e2, e2); fma2(acc[2][0], en01, ee); fma2(acc[2][1], en23, ee);
                ee = pack2(e3, e3); fma2(acc[3][0], en01, ee); fma2(acc[3][1], en23, ee);
            }
        }
    }

    __syncthreads();
    if (ts == 1) {
        float* dst = encs + (size_t)(jg * 32 + lane) * 16;
#pragma unroll
        for (int j = 0; j < 4; j++) {
            unpack2(acc[j][0], dst[j * 4 + 0], dst[j * 4 + 1]);
            unpack2(acc[j][1], dst[j * 4 + 2], dst[j * 4 + 3]);
        }
    }
    __syncthreads();
    if (ts == 0) {
        const float* src = encs + (size_t)(jg * 32 + lane) * 16;
        int jbase = b * TD + jb * JT + jg * 4;
#pragma unroll
        for (int j = 0; j < 4; j++) {
            float x0, x1, x2, x3;
            unpack2(acc[j][0], x0, x1);
            unpack2(acc[j][1], x2, x3);
            float4 r = make_float4(x0 + src[j * 4 + 0], x1 + src[j * 4 + 1],
                                   x2 + src[j * 4 + 2], x3 + src[j * 4 + 3]);
            *(float4*)(c + (size_t)(jbase + j) * HH + 4 * lane) = r;
        }
    }
}

// ---------------------------------------------------------------------------
// Launch: c_outputs [B,TD,H] then e_outputs [B,TD,TE], flattened in order.
// ---------------------------------------------------------------------------
extern "C" void kernel_launch(void* const* d_in, const int* in_sizes, int n_in,
                              void* d_out, int out_size) {
    const float* enc = (const float*)d_in[0];   // [B,TE,H]
    const float* dec = (const float*)d_in[1];   // [B,TD,D]
    const float* Wa  = (const float*)d_in[2];   // [H,H]
    const float* Ua  = (const float*)d_in[3];   // [D,H]
    const float* Va  = (const float*)d_in[4];   // [H,1]

    float* out   = (float*)d_out;
    float* c_out = out;                          // B*TD*H
    float* e_out = out + (size_t)BB * TD * HH;   // B*TD*TE

    proj_kernel<<<BB * TE / 32 + BB * TD / 32, 256>>>(enc, dec, Wa, Ua);
    score_kernel<<<dim3(TE / TT, TD / TJ, BB), 256>>>(Va, e_out);
    context_kernel<<<BB * TD / JT, 256>>>(enc, e_out, c_out);
}